// round 6
// baseline (speedup 1.0000x reference)
#include <cuda_runtime.h>
#include <math.h>

#define DINL __device__ __forceinline__
typedef unsigned long long ull;

DINL float silu_f(float x) { return x / (1.f + expf(-x)); }
DINL float sigm_f(float x) { return 1.f / (1.f + expf(-x)); }

// ---------------- packed f32x2 helpers (sm_100+) ----------------
DINL ull pk2(float x) { ull r; asm("mov.b64 %0,{%1,%1};" : "=l"(r) : "f"(x)); return r; }
DINL ull pkpair(float a, float b) { ull r; asm("mov.b64 %0,{%1,%2};" : "=l"(r) : "f"(a), "f"(b)); return r; }
DINL ull f2fma(ull a, ull b, ull c) {
    ull d; asm("fma.rn.f32x2 %0,%1,%2,%3;" : "=l"(d) : "l"(a), "l"(b), "l"(c)); return d;
}
DINL float2 upk(ull a) { float lo, hi; asm("mov.b64 {%0,%1},%2;" : "=f"(lo), "=f"(hi) : "l"(a)); return make_float2(lo, hi); }

// ------------------------- scratch (device globals) ------------------------
__device__ float g_x[2 * 3 * 256 * 256];
__device__ float g_c1[2 * 32 * 128 * 128];
__device__ float g_c2[2 * 64 * 64 * 64];
__device__ float g_c3[2 * 128 * 32 * 32];
__device__ float g_c4[2 * 256 * 16 * 16];
__device__ float g_feat[2 * 480 * 8 * 8];
__device__ float g_h1[2 * 128 * 8 * 8];
__device__ float g_wT[4320 * 128];
__device__ float g_lpart[30 * 2 * 128 * 8 * 8];
__device__ float g_cpart[4194304];               // split-K partials (16MB)
__device__ float g_wrep[387936];
__device__ float g_G[2 * 3 * 8 * 8 * 256 * 2];   // fused weight*LUT table (G0, dG)

#define WR1_OFF 0
#define WR2_OFF 864
#define WR3_OFF 19296
#define WR4_OFF 93024

// ---------------- prep: all conv weight repacks + lin1 transpose -----------
__global__ void prep_kernel(const float* __restrict__ w1, const float* __restrict__ w2,
                            const float* __restrict__ w3, const float* __restrict__ w4,
                            const float* __restrict__ lw, float* __restrict__ wrep,
                            float* __restrict__ wT) {
    int idx = blockIdx.x * 256 + threadIdx.x;
    if (idx < 864) {
        int oc = idx % 32, p = (idx / 32) % 9, ic = idx / 288;
        wrep[WR1_OFF + idx] = w1[(oc * 3 + ic) * 9 + p];
    } else if (idx < 864 + 18432) {
        int j = idx - 864;
        int oc = j % 64, p = (j / 64) % 9, ic = j / 576;
        wrep[WR2_OFF + j] = w2[(oc * 32 + ic) * 9 + p];
    } else if (idx < 19296 + 73728) {
        int j = idx - 19296;
        int oc = j % 128, p = (j / 128) % 9, ic = j / 1152;
        wrep[WR3_OFF + j] = w3[(oc * 64 + ic) * 9 + p];
    } else if (idx < 93024 + 294912) {
        int j = idx - 93024;
        int oc = j % 256, p = (j / 256) % 9, ic = j / 2304;
        wrep[WR4_OFF + j] = w4[(oc * 128 + ic) * 9 + p];
    } else if (idx < 387936 + 552960) {
        int j = idx - 387936;
        int k = j >> 7, oc = j & 127;
        wT[j] = lw[(long)oc * 4320 + k];
    }
}

// ------------------------------ resize 1024->256 ---------------------------
__global__ void resize256_kernel(const float* __restrict__ img, float* __restrict__ out) {
    int idx = blockIdx.x * blockDim.x + threadIdx.x;
    if (idx >= 2 * 3 * 256 * 256) return;
    int ox = idx & 255;
    int oy = (idx >> 8) & 255;
    int bc = idx >> 16;
    const float scale = 1023.0f / 255.0f;
    float py = oy * scale;
    int iy = (int)py; if (iy > 1022) iy = 1022;
    float fy = py - (float)iy;
    float px = ox * scale;
    int ix = (int)px; if (ix > 1022) ix = 1022;
    float fx = px - (float)ix;
    const float* p = img + ((long)bc << 20) + iy * 1024 + ix;
    float v00 = p[0], v01 = p[1], v10 = p[1024], v11 = p[1025];
    float c0 = v00 + fy * (v10 - v00);
    float c1 = v01 + fy * (v11 - v01);
    out[idx] = c0 + fx * (c1 - c0);
}

// ------ stride-2 3x3 conv, reflect pad, fat register tile, f32x2, split-K ----
// Thread: 8 oc x OWT ow. Direct gmem loads (weights broadcast within warp).
template <int ICC, int OC, int H, int OWT, bool FUSE>
__global__ __launch_bounds__(256, 2) void conv_fat(
    const float* __restrict__ in, const float* __restrict__ wrep,
    const float* __restrict__ bias, float* __restrict__ out, int ICtot) {
    constexpr int OH = H / 2, OW = H / 2;
    constexpr int QW = OW / OWT;
    constexpr int NX = 2 * OWT + 1;      // input cols rel -1 .. 2*OWT-1
    constexpr int TOTAL = 2 * (OC / 8) * OH * QW;
    constexpr int NOUT = 2 * OC * OH * OW;

    int idx = blockIdx.x * 256 + threadIdx.x;
    if (idx >= TOTAL) return;
    int ks = blockIdx.y;
    int ic0 = ks * ICC;

    int q = idx % QW;
    int oh = (idx / QW) % OH;
    int ocg = (idx / (QW * OH)) % (OC / 8);
    int b = idx / (QW * OH * (OC / 8));
    int ow0 = q * OWT;
    int oc0 = ocg * 8;

    int rr[3];
#pragma unroll
    for (int kh = 0; kh < 3; kh++) { int r = 2 * oh - 1 + kh; rr[kh] = (r < 0) ? -r : r; }

    ull acc[4][OWT];
#pragma unroll
    for (int o2 = 0; o2 < 4; o2++) {
        ull bv = (ks == 0) ? pkpair(bias[oc0 + 2 * o2], bias[oc0 + 2 * o2 + 1]) : 0ull;
#pragma unroll
        for (int j = 0; j < OWT; j++) acc[o2][j] = bv;
    }

    const float* wbase = wrep + (long)ic0 * 9 * OC + oc0;

    for (int ic = 0; ic < ICC; ic++) {
        const float* ip = in + (long)(b * ICtot + ic0 + ic) * H * H;
        const float* wp = wbase + (long)ic * 9 * OC;
#pragma unroll
        for (int kh = 0; kh < 3; kh++) {
            const float* rp = ip + rr[kh] * H;
            float x[NX];  // x[k] = input col (2*ow0 - 1 + k)
            if (ow0) {
                const float2* r2 = (const float2*)(rp + 2 * ow0 - 2);
                float v[2 * OWT + 2];
#pragma unroll
                for (int t = 0; t < OWT + 1; t++) {
                    float2 d = __ldg(r2 + t);
                    v[2 * t] = d.x; v[2 * t + 1] = d.y;
                }
#pragma unroll
                for (int k = 0; k < NX; k++) x[k] = v[k + 1];
            } else {
                const float2* r2 = (const float2*)rp;
                float v[2 * OWT];
#pragma unroll
                for (int t = 0; t < OWT; t++) {
                    float2 d = __ldg(r2 + t);
                    v[2 * t] = d.x; v[2 * t + 1] = d.y;
                }
                x[0] = v[1];  // reflect col -1 -> col 1
#pragma unroll
                for (int k = 1; k < NX; k++) x[k] = v[k - 1];
            }
            ull xx[NX];
#pragma unroll
            for (int k = 0; k < NX; k++) xx[k] = pk2(x[k]);
#pragma unroll
            for (int kw = 0; kw < 3; kw++) {
                const ulonglong2* w2p = (const ulonglong2*)(wp + (kh * 3 + kw) * OC);
                ulonglong2 wa = __ldg(w2p);
                ulonglong2 wb = __ldg(w2p + 1);
                ull wv[4] = {wa.x, wa.y, wb.x, wb.y};
#pragma unroll
                for (int o2 = 0; o2 < 4; o2++)
#pragma unroll
                    for (int j = 0; j < OWT; j++)
                        acc[o2][j] = f2fma(wv[o2], xx[2 * j + kw], acc[o2][j]);
            }
        }
    }

    float* ob = out + (FUSE ? 0l : (long)ks * NOUT);
#pragma unroll
    for (int o2 = 0; o2 < 4; o2++) {
        float ev[OWT], od[OWT];
#pragma unroll
        for (int j = 0; j < OWT; j++) {
            float2 p = upk(acc[o2][j]);
            ev[j] = FUSE ? silu_f(p.x) : p.x;
            od[j] = FUSE ? silu_f(p.y) : p.y;
        }
        long oe = ((long)(b * OC + oc0 + 2 * o2) * OH + oh) * OW + ow0;
#pragma unroll
        for (int j4 = 0; j4 < OWT / 4; j4++) {
            *(float4*)(ob + oe + 4 * j4) =
                make_float4(ev[4 * j4], ev[4 * j4 + 1], ev[4 * j4 + 2], ev[4 * j4 + 3]);
            *(float4*)(ob + oe + (long)OH * OW + 4 * j4) =
                make_float4(od[4 * j4], od[4 * j4 + 1], od[4 * j4 + 2], od[4 * j4 + 3]);
        }
    }
}

// ----------------------- split-K reduce + SiLU epilogue ---------------------
__global__ void reduce_silu_kernel(const float* __restrict__ part, float* __restrict__ out,
                                   int n, int ks) {
    int idx = blockIdx.x * blockDim.x + threadIdx.x;
    if (idx >= n) return;
    float s = 0.f;
    for (int k = 0; k < ks; k++) s += part[k * n + idx];
    out[idx] = silu_f(s);
}

// ----------------------- merged avg pools (warp/output) ---------------------
__global__ void pool_all_kernel(const float* __restrict__ c1, const float* __restrict__ c2,
                                const float* __restrict__ c3, const float* __restrict__ c4,
                                float* __restrict__ feat) {
    int gw = (blockIdx.x * blockDim.x + threadIdx.x) >> 5;
    int lane = threadIdx.x & 31;
    if (gw >= 2 * 480 * 64) return;
    int x = gw & 7;
    int y = (gw >> 3) & 7;
    int cg = (gw >> 6) % 480;
    int b = gw / (480 * 64);
    const float* src; int C, H, k, c;
    if (cg < 32)       { src = c1; C = 32;  H = 128; k = 16; c = cg; }
    else if (cg < 96)  { src = c2; C = 64;  H = 64;  k = 8;  c = cg - 32; }
    else if (cg < 224) { src = c3; C = 128; H = 32;  k = 4;  c = cg - 96; }
    else               { src = c4; C = 256; H = 16;  k = 2;  c = cg - 224; }
    const float* base = src + ((long)(b * C + c) * H + y * k) * H + x * k;
    float s = 0.f;
    int kk = k * k;
    for (int i = lane; i < kk; i += 32) s += base[(i / k) * H + (i % k)];
#pragma unroll
    for (int off = 16; off > 0; off >>= 1) s += __shfl_down_sync(0xffffffffu, s, off);
    if (lane == 0) feat[((b * 480 + cg) * 8 + y) * 8 + x] = s * (1.f / (float)kk);
}

// ----------------- lin1: 3x3 reflect conv 480->128 on 8x8 -------------------
__global__ __launch_bounds__(128) void lin1_kernel(const float* __restrict__ feat,
                                                   const float* __restrict__ wT,
                                                   float* __restrict__ part) {
    __shared__ float slab[16 * 3 * 8];
    int kc = blockIdx.x;
    int oh = blockIdx.y;
    int b = blockIdx.z;
    int t = threadIdx.x;
    int ic0 = kc * 16;

    int ihs[3];
#pragma unroll
    for (int kh = 0; kh < 3; kh++) {
        int r = oh - 1 + kh;
        if (r < 0) r = -r;
        if (r > 7) r = 14 - r;
        ihs[kh] = r;
    }
    for (int j = t; j < 384; j += 128) {
        int icl = j / 24;
        int rem = j % 24;
        int r = rem / 8, col = rem % 8;
        slab[j] = feat[((b * 480 + ic0 + icl) * 8 + ihs[r]) * 8 + col];
    }
    __syncthreads();

    float acc[8];
#pragma unroll
    for (int ow = 0; ow < 8; ow++) acc[ow] = 0.f;

    const int IWT[10] = {1, 0, 1, 2, 3, 4, 5, 6, 7, 6};
#pragma unroll 2
    for (int icl = 0; icl < 16; icl++) {
        float rv[3][8];
#pragma unroll
        for (int r = 0; r < 3; r++)
#pragma unroll
            for (int col = 0; col < 8; col++) rv[r][col] = slab[icl * 24 + r * 8 + col];
#pragma unroll
        for (int kh = 0; kh < 3; kh++)
#pragma unroll
            for (int kw = 0; kw < 3; kw++) {
                float wv = __ldg(wT + (long)((ic0 + icl) * 9 + kh * 3 + kw) * 128 + t);
#pragma unroll
                for (int ow = 0; ow < 8; ow++) acc[ow] += wv * rv[kh][IWT[ow + kw]];
            }
    }
    int base = (((kc * 2 + b) * 128 + t) * 8 + oh) * 8;
#pragma unroll
    for (int ow = 0; ow < 8; ow++) part[base + ow] = acc[ow];
}

__global__ void lin1_reduce_kernel(const float* __restrict__ part,
                                   const float* __restrict__ bias, float* __restrict__ h1) {
    int idx = blockIdx.x * blockDim.x + threadIdx.x;
    if (idx >= 16384) return;
    int oc = (idx >> 6) & 127;
    float s = bias[oc];
#pragma unroll 6
    for (int kc = 0; kc < 30; kc++) s += part[kc * 16384 + idx];
    h1[idx] = silu_f(s);
}

// ---- fused lin2 (1x1 conv 128->27 + sigmoid) + G table build ---------------
__global__ __launch_bounds__(256) void gprep2_kernel(
    const float* __restrict__ h1, const float* __restrict__ w2,
    const float* __restrict__ b2, const float* __restrict__ luts,
    float* __restrict__ G) {
    int gy = blockIdx.x & 7;
    int c = (blockIdx.x >> 3) % 3;
    int b = blockIdx.x / 24;
    __shared__ float sh1[128][8];
    __shared__ float wk[9][8];
    int tid = threadIdx.x;
    for (int j = tid; j < 1024; j += 256) {
        int ic = j >> 3, gx = j & 7;
        sh1[ic][gx] = h1[(b * 128 + ic) * 64 + gy * 8 + gx];
    }
    __syncthreads();
    if (tid < 72) {
        int k = tid >> 3, gx = tid & 7;
        float acc = b2[c * 9 + k];
        const float* wp = w2 + (c * 9 + k) * 128;
#pragma unroll 8
        for (int ic = 0; ic < 128; ic++) acc = fmaf(__ldg(wp + ic), sh1[ic][gx], acc);
        wk[k][gx] = sigm_f(acc);
    }
    __syncthreads();
    for (int j = tid; j < 2048; j += 256) {
        int gx = j >> 8;
        int i = j & 255;
        float g0 = 0.f, g1 = 0.f;
#pragma unroll
        for (int k = 0; k < 9; k++) {
            const float* lp = luts + (c * 9 + k) * 256;
            float l0 = lp[i];
            float l1 = (i < 255) ? lp[i + 1] : l0;
            g0 = fmaf(wk[k][gx], l0, g0);
            g1 = fmaf(wk[k][gx], l1, g1);
        }
        long o = ((((long)(b * 3 + c) * 8 + gy) * 8 + gx) * 256 + i) * 2;
        G[o] = g0;
        G[o + 1] = g1 - g0;
    }
}

// --------- final: per-pixel 4-corner gather from fused G table --------------
__global__ __launch_bounds__(512) void final_v3(const float* __restrict__ img,
                                                const float* __restrict__ G,
                                                float* __restrict__ out) {
    extern __shared__ float sG[];  // 36864 floats = 147456 B
    int rg = blockIdx.x;
    int b = blockIdx.y;
    int tid = threadIdx.x;
    int h0 = rg * 16;
    const float sc = 7.0f / 1023.0f;

    int g0row = (int)(h0 * sc); if (g0row > 6) g0row = 6;
    int gy_base = (g0row > 5) ? 5 : g0row;

    for (int j = tid; j < 9216; j += 512) {
        int cg = j / 1024;
        int r = j % 1024;
        int c = cg / 3, gyl = cg % 3;
        long src = (((long)(b * 3 + c) * 8 + (gy_base + gyl)) * 8) * 512;
        ((float4*)sG)[cg * 1024 + r] = *(const float4*)(G + src + r * 4);
    }
    __syncthreads();

    int w0 = tid * 2;
    int gxp[2]; float fwp[2];
#pragma unroll
    for (int px = 0; px < 2; px++) {
        float pwv = (w0 + px) * sc;
        int gx = (int)pwv; if (gx > 6) gx = 6;
        gxp[px] = gx;
        fwp[px] = pwv - (float)gx;
    }

    const float2* sgp = (const float2*)sG;

    for (int r = 0; r < 16; r++) {
        int h = h0 + r;
        float ph = h * sc;
        int gy0 = (int)ph; if (gy0 > 6) gy0 = 6;
        float fh = ph - (float)gy0;
        int gyl = gy0 - gy_base;

#pragma unroll
        for (int c = 0; c < 3; c++) {
            long ib = ((long)(b * 3 + c) << 20) + ((long)h << 10) + w0;
            float2 iv = *(const float2*)(img + ib);
            float2 res;
            const float2* crow = sgp + (c * 3 + gyl) * 2048;
#pragma unroll
            for (int px = 0; px < 2; px++) {
                float v = px ? iv.y : iv.x;
                float p = fminf(fmaxf(v, 0.f), 1.f) * 255.0f;
                int i0 = (int)p; if (i0 > 254) i0 = 254;
                float fr = p - (float)i0;
                const float2* b00 = crow + gxp[px] * 256;
                float2 A = b00[i0];
                float2 Bv = b00[256 + i0];
                float2 Cv = b00[2048 + i0];
                float2 Dv = b00[2048 + 256 + i0];
                float va = fmaf(fr, A.y, A.x);
                float vb = fmaf(fr, Bv.y, Bv.x);
                float vc = fmaf(fr, Cv.y, Cv.x);
                float vd = fmaf(fr, Dv.y, Dv.x);
                float fw = fwp[px];
                float top = fmaf(fw, vb - va, va);
                float bot = fmaf(fw, vd - vc, vc);
                float rv = fmaf(fh, bot - top, top);
                rv = fminf(fmaxf(rv, 0.f), 1.f);
                if (px) res.y = rv; else res.x = rv;
            }
            *(float2*)(out + ib) = res;
        }
    }
}

// --------------------------------- launch ----------------------------------
extern "C" void kernel_launch(void* const* d_in, const int* in_sizes, int n_in,
                              void* d_out, int out_size) {
    const float* img     = (const float*)d_in[0];
    const float* conv1_w = (const float*)d_in[1];
    const float* conv1_b = (const float*)d_in[2];
    const float* conv2_w = (const float*)d_in[3];
    const float* conv2_b = (const float*)d_in[4];
    const float* conv3_w = (const float*)d_in[5];
    const float* conv3_b = (const float*)d_in[6];
    const float* conv4_w = (const float*)d_in[7];
    const float* conv4_b = (const float*)d_in[8];
    const float* lin1_w  = (const float*)d_in[9];
    const float* lin1_b  = (const float*)d_in[10];
    const float* lin2_w  = (const float*)d_in[11];
    const float* lin2_b  = (const float*)d_in[12];
    const float* luts    = (const float*)d_in[13];
    float* out = (float*)d_out;

    float *px, *pc1, *pc2, *pc3, *pc4, *pfeat, *ph1, *pwT, *plp, *pcp, *pwr, *pG;
    cudaGetSymbolAddress((void**)&px, g_x);
    cudaGetSymbolAddress((void**)&pc1, g_c1);
    cudaGetSymbolAddress((void**)&pc2, g_c2);
    cudaGetSymbolAddress((void**)&pc3, g_c3);
    cudaGetSymbolAddress((void**)&pc4, g_c4);
    cudaGetSymbolAddress((void**)&pfeat, g_feat);
    cudaGetSymbolAddress((void**)&ph1, g_h1);
    cudaGetSymbolAddress((void**)&pwT, g_wT);
    cudaGetSymbolAddress((void**)&plp, g_lpart);
    cudaGetSymbolAddress((void**)&pcp, g_cpart);
    cudaGetSymbolAddress((void**)&pwr, g_wrep);
    cudaGetSymbolAddress((void**)&pG, g_G);

    cudaFuncSetAttribute(final_v3, cudaFuncAttributeMaxDynamicSharedMemorySize, 147456);

    // 0. prep: weight repacks + lin1 transpose
    prep_kernel<<<3676, 256>>>(conv1_w, conv2_w, conv3_w, conv4_w, lin1_w, pwr, pwT);

    // 1. resize 1024 -> 256
    resize256_kernel<<<1536, 256>>>(img, px);

    // 2-5. fat-tile conv stack (8 oc x OWT ow per thread, split-K)
    // conv1: IC=3, no split, fused SiLU, OWT=4 -> 128 blocks
    conv_fat<3, 32, 256, 4, true><<<dim3(128, 1), 256>>>(px, pwr + WR1_OFF, conv1_b, pc1, 3);

    // conv2: ICC=4, ks=8 -> 32 x 8 = 256 blocks
    conv_fat<4, 64, 128, 8, false><<<dim3(32, 8), 256>>>(pc1, pwr + WR2_OFF, conv2_b, pcp, 32);
    reduce_silu_kernel<<<2048, 256>>>(pcp, pc2, 524288, 8);

    // conv3: ICC=4, ks=16 -> 16 x 16 = 256 blocks
    conv_fat<4, 128, 64, 8, false><<<dim3(16, 16), 256>>>(pc2, pwr + WR3_OFF, conv3_b, pcp, 64);
    reduce_silu_kernel<<<1024, 256>>>(pcp, pc3, 262144, 16);

    // conv4: ICC=4, ks=32 -> 8 x 32 = 256 blocks
    conv_fat<4, 256, 32, 8, false><<<dim3(8, 32), 256>>>(pc3, pwr + WR4_OFF, conv4_b, pcp, 128);
    reduce_silu_kernel<<<512, 256>>>(pcp, pc4, 131072, 32);

    // 6. merged multi-scale avg pools
    pool_all_kernel<<<7680, 256>>>(pc1, pc2, pc3, pc4, pfeat);

    // 7. lin1 (480->128, 3x3 reflect, SiLU), split-K x30
    lin1_kernel<<<dim3(30, 8, 2), 128>>>(pfeat, pwT, plp);
    lin1_reduce_kernel<<<64, 256>>>(plp, lin1_b, ph1);

    // 8+9. fused lin2 + G table
    gprep2_kernel<<<48, 256>>>(ph1, lin2_w, lin2_b, luts, pG);

    // 10. final: 4-corner gather + clip
    final_v3<<<dim3(64, 2), 512, 147456>>>(img, pG, out);
}

// round 7
// speedup vs baseline: 2.0524x; 2.0524x over previous
#include <cuda_runtime.h>
#include <math.h>

#define DINL __device__ __forceinline__
typedef unsigned long long ull;

DINL float silu_f(float x) { return x / (1.f + expf(-x)); }
DINL float sigm_f(float x) { return 1.f / (1.f + expf(-x)); }

// ---------------- packed f32x2 helpers (sm_100+) ----------------
DINL ull pk2(float x) { ull r; asm("mov.b64 %0,{%1,%1};" : "=l"(r) : "f"(x)); return r; }
DINL ull pkpair(float a, float b) { ull r; asm("mov.b64 %0,{%1,%2};" : "=l"(r) : "f"(a), "f"(b)); return r; }
DINL ull f2fma(ull a, ull b, ull c) {
    ull d; asm("fma.rn.f32x2 %0,%1,%2,%3;" : "=l"(d) : "l"(a), "l"(b), "l"(c)); return d;
}
DINL float2 upk(ull a) { float lo, hi; asm("mov.b64 {%0,%1},%2;" : "=f"(lo), "=f"(hi) : "l"(a)); return make_float2(lo, hi); }

// ------------------------- scratch (device globals) ------------------------
__device__ float g_x[2 * 3 * 256 * 256];
__device__ float g_c1[2 * 32 * 128 * 128];
__device__ float g_c2[2 * 64 * 64 * 64];
__device__ float g_c3[2 * 128 * 32 * 32];
__device__ float g_c4[2 * 256 * 16 * 16];
__device__ float g_feat[2 * 480 * 8 * 8];
__device__ float g_h1[2 * 128 * 8 * 8];
__device__ float g_wT[4320 * 128];
__device__ float g_lpart[30 * 2 * 128 * 8 * 8];
__device__ float g_cpart[2097152];
__device__ float g_wrep[387936];
__device__ float g_G[2 * 3 * 8 * 8 * 256 * 2];   // fused weight*LUT table (G0, dG)

#define WR1_OFF 0
#define WR2_OFF 864
#define WR3_OFF 19296
#define WR4_OFF 93024

// ---------------- prep: all conv weight repacks + lin1 transpose -----------
__global__ void prep_kernel(const float* __restrict__ w1, const float* __restrict__ w2,
                            const float* __restrict__ w3, const float* __restrict__ w4,
                            const float* __restrict__ lw, float* __restrict__ wrep,
                            float* __restrict__ wT) {
    int idx = blockIdx.x * 256 + threadIdx.x;
    if (idx < 864) {
        int oc = idx % 32, p = (idx / 32) % 9, ic = idx / 288;
        wrep[WR1_OFF + idx] = w1[(oc * 3 + ic) * 9 + p];
    } else if (idx < 864 + 18432) {
        int j = idx - 864;
        int oc = j % 64, p = (j / 64) % 9, ic = j / 576;
        wrep[WR2_OFF + j] = w2[(oc * 32 + ic) * 9 + p];
    } else if (idx < 19296 + 73728) {
        int j = idx - 19296;
        int oc = j % 128, p = (j / 128) % 9, ic = j / 1152;
        wrep[WR3_OFF + j] = w3[(oc * 64 + ic) * 9 + p];
    } else if (idx < 93024 + 294912) {
        int j = idx - 93024;
        int oc = j % 256, p = (j / 256) % 9, ic = j / 2304;
        wrep[WR4_OFF + j] = w4[(oc * 128 + ic) * 9 + p];
    } else if (idx < 387936 + 552960) {
        int j = idx - 387936;
        int k = j >> 7, oc = j & 127;
        wT[j] = lw[(long)oc * 4320 + k];
    }
}

// ------------------------------ resize 1024->256 ---------------------------
__global__ void resize256_kernel(const float* __restrict__ img, float* __restrict__ out) {
    int idx = blockIdx.x * blockDim.x + threadIdx.x;
    if (idx >= 2 * 3 * 256 * 256) return;
    int ox = idx & 255;
    int oy = (idx >> 8) & 255;
    int bc = idx >> 16;
    const float scale = 1023.0f / 255.0f;
    float py = oy * scale;
    int iy = (int)py; if (iy > 1022) iy = 1022;
    float fy = py - (float)iy;
    float px = ox * scale;
    int ix = (int)px; if (ix > 1022) ix = 1022;
    float fx = px - (float)ix;
    const float* p = img + ((long)bc << 20) + iy * 1024 + ix;
    float v00 = p[0], v01 = p[1], v10 = p[1024], v11 = p[1025];
    float c0 = v00 + fy * (v10 - v00);
    float c1 = v01 + fy * (v11 - v01);
    out[idx] = c0 + fx * (c1 - c0);
}

// --- stride-2 3x3 conv, reflect pad, f32x2, split-K, ocg-fastest lane map ----
// Thread: 8 oc x 4 ow. Lanes within a warp differ in ocg first -> input loads
// land in 1-2 L1 lines per instruction instead of 8.
template <int ICC, int OC, int H, bool FUSE>
__global__ __launch_bounds__(256, 2) void conv_v3(
    const float* __restrict__ in, const float* __restrict__ wrep,
    const float* __restrict__ bias, float* __restrict__ out, int ICtot) {
    constexpr int OH = H / 2;
    constexpr int OW = H / 2;
    constexpr int QW = OW / 4;
    constexpr int NOCG = OC / 8;
    constexpr int TOTAL = 2 * NOCG * OH * QW;
    constexpr int NOUT = 2 * OC * OH * OW;
    int idx = blockIdx.x * 256 + threadIdx.x;
    if (idx >= TOTAL) return;
    int ks = blockIdx.y;
    int ic0 = ks * ICC;

    // ocg fastest within warp
    int ocg = idx % NOCG;
    int q = (idx / NOCG) % QW;
    int oh = (idx / (NOCG * QW)) % OH;
    int b = idx / (NOCG * QW * OH);
    int ow0 = q * 4;
    int oc0 = ocg * 8;
    int base = 2 * ow0;

    int rr[3];
#pragma unroll
    for (int kh = 0; kh < 3; kh++) { int r = 2 * oh - 1 + kh; rr[kh] = (r < 0) ? -r : r; }

    ull acc[4][4];
#pragma unroll
    for (int o2 = 0; o2 < 4; o2++) {
        ull bv = (ks == 0) ? pkpair(bias[oc0 + 2 * o2], bias[oc0 + 2 * o2 + 1]) : 0ull;
#pragma unroll
        for (int j = 0; j < 4; j++) acc[o2][j] = bv;
    }

    const float* wbase = wrep + (long)ic0 * 9 * OC + oc0;

    for (int ic = 0; ic < ICC; ic++) {
        const float* ip = in + (long)(b * ICtot + ic0 + ic) * H * H;
        const float* wp = wbase + (long)ic * 9 * OC;
#pragma unroll
        for (int kh = 0; kh < 3; kh++) {
            const float* rp = ip + rr[kh] * H;
            float v[10];  // cols base-2 .. base+7
            if (base) {
                const float2* r2 = (const float2*)(rp + base - 2);
#pragma unroll
                for (int t = 0; t < 5; t++) { float2 d = __ldg(r2 + t); v[2 * t] = d.x; v[2 * t + 1] = d.y; }
            } else {
                const float2* r2 = (const float2*)rp;
#pragma unroll
                for (int t = 0; t < 4; t++) { float2 d = __ldg(r2 + t); v[2 + 2 * t] = d.x; v[3 + 2 * t] = d.y; }
                v[1] = v[3];  // reflect: col -1 -> col 1
                v[0] = 0.f;
            }
            ull xx[9];
#pragma unroll
            for (int i = 0; i < 9; i++) xx[i] = pk2(v[i + 1]);
#pragma unroll
            for (int kw = 0; kw < 3; kw++) {
                const ulonglong2* w2p = (const ulonglong2*)(wp + (kh * 3 + kw) * OC);
                ulonglong2 wa = __ldg(w2p);
                ulonglong2 wb = __ldg(w2p + 1);
                ull wv[4] = {wa.x, wa.y, wb.x, wb.y};
#pragma unroll
                for (int o2 = 0; o2 < 4; o2++)
#pragma unroll
                    for (int j = 0; j < 4; j++)
                        acc[o2][j] = f2fma(wv[o2], xx[2 * j + kw], acc[o2][j]);
            }
        }
    }

    float* ob = out + (FUSE ? 0l : (long)ks * NOUT);
#pragma unroll
    for (int o2 = 0; o2 < 4; o2++) {
        float2 p0 = upk(acc[o2][0]), p1 = upk(acc[o2][1]), p2 = upk(acc[o2][2]), p3 = upk(acc[o2][3]);
        float ev0 = p0.x, ev1 = p1.x, ev2 = p2.x, ev3 = p3.x;
        float od0 = p0.y, od1 = p1.y, od2 = p2.y, od3 = p3.y;
        if (FUSE) {
            ev0 = silu_f(ev0); ev1 = silu_f(ev1); ev2 = silu_f(ev2); ev3 = silu_f(ev3);
            od0 = silu_f(od0); od1 = silu_f(od1); od2 = silu_f(od2); od3 = silu_f(od3);
        }
        long oe = ((long)(b * OC + oc0 + 2 * o2) * OH + oh) * OW + ow0;
        *(float4*)(ob + oe) = make_float4(ev0, ev1, ev2, ev3);
        *(float4*)(ob + oe + (long)OH * OW) = make_float4(od0, od1, od2, od3);
    }
}

// ----------------------- split-K reduce + SiLU epilogue ---------------------
__global__ void reduce_silu_kernel(const float* __restrict__ part, float* __restrict__ out,
                                   int n, int ks) {
    int idx = blockIdx.x * blockDim.x + threadIdx.x;
    if (idx >= n) return;
    float s = 0.f;
    for (int k = 0; k < ks; k++) s += part[k * n + idx];
    out[idx] = silu_f(s);
}

// ----------------------- merged avg pools (warp/output) ---------------------
__global__ void pool_all_kernel(const float* __restrict__ c1, const float* __restrict__ c2,
                                const float* __restrict__ c3, const float* __restrict__ c4,
                                float* __restrict__ feat) {
    int gw = (blockIdx.x * blockDim.x + threadIdx.x) >> 5;
    int lane = threadIdx.x & 31;
    if (gw >= 2 * 480 * 64) return;
    int x = gw & 7;
    int y = (gw >> 3) & 7;
    int cg = (gw >> 6) % 480;
    int b = gw / (480 * 64);
    const float* src; int C, H, k, c;
    if (cg < 32)       { src = c1; C = 32;  H = 128; k = 16; c = cg; }
    else if (cg < 96)  { src = c2; C = 64;  H = 64;  k = 8;  c = cg - 32; }
    else if (cg < 224) { src = c3; C = 128; H = 32;  k = 4;  c = cg - 96; }
    else               { src = c4; C = 256; H = 16;  k = 2;  c = cg - 224; }
    const float* base = src + ((long)(b * C + c) * H + y * k) * H + x * k;
    float s = 0.f;
    int kk = k * k;
    for (int i = lane; i < kk; i += 32) s += base[(i / k) * H + (i % k)];
#pragma unroll
    for (int off = 16; off > 0; off >>= 1) s += __shfl_down_sync(0xffffffffu, s, off);
    if (lane == 0) feat[((b * 480 + cg) * 8 + y) * 8 + x] = s * (1.f / (float)kk);
}

// ----------------- lin1: 3x3 reflect conv 480->128 on 8x8 -------------------
__global__ __launch_bounds__(128) void lin1_kernel(const float* __restrict__ feat,
                                                   const float* __restrict__ wT,
                                                   float* __restrict__ part) {
    __shared__ float slab[16 * 3 * 8];
    int kc = blockIdx.x;
    int oh = blockIdx.y;
    int b = blockIdx.z;
    int t = threadIdx.x;
    int ic0 = kc * 16;

    int ihs[3];
#pragma unroll
    for (int kh = 0; kh < 3; kh++) {
        int r = oh - 1 + kh;
        if (r < 0) r = -r;
        if (r > 7) r = 14 - r;
        ihs[kh] = r;
    }
    for (int j = t; j < 384; j += 128) {
        int icl = j / 24;
        int rem = j % 24;
        int r = rem / 8, col = rem % 8;
        slab[j] = feat[((b * 480 + ic0 + icl) * 8 + ihs[r]) * 8 + col];
    }
    __syncthreads();

    float acc[8];
#pragma unroll
    for (int ow = 0; ow < 8; ow++) acc[ow] = 0.f;

    const int IWT[10] = {1, 0, 1, 2, 3, 4, 5, 6, 7, 6};
#pragma unroll 2
    for (int icl = 0; icl < 16; icl++) {
        float rv[3][8];
#pragma unroll
        for (int r = 0; r < 3; r++)
#pragma unroll
            for (int col = 0; col < 8; col++) rv[r][col] = slab[icl * 24 + r * 8 + col];
#pragma unroll
        for (int kh = 0; kh < 3; kh++)
#pragma unroll
            for (int kw = 0; kw < 3; kw++) {
                float wv = __ldg(wT + (long)((ic0 + icl) * 9 + kh * 3 + kw) * 128 + t);
#pragma unroll
                for (int ow = 0; ow < 8; ow++) acc[ow] += wv * rv[kh][IWT[ow + kw]];
            }
    }
    int base = (((kc * 2 + b) * 128 + t) * 8 + oh) * 8;
#pragma unroll
    for (int ow = 0; ow < 8; ow++) part[base + ow] = acc[ow];
}

__global__ void lin1_reduce_kernel(const float* __restrict__ part,
                                   const float* __restrict__ bias, float* __restrict__ h1) {
    int idx = blockIdx.x * blockDim.x + threadIdx.x;
    if (idx >= 16384) return;
    int oc = (idx >> 6) & 127;
    float s = bias[oc];
#pragma unroll 6
    for (int kc = 0; kc < 30; kc++) s += part[kc * 16384 + idx];
    h1[idx] = silu_f(s);
}

// ---- fused lin2 (1x1 conv 128->27 + sigmoid) + G table build ---------------
__global__ __launch_bounds__(256) void gprep2_kernel(
    const float* __restrict__ h1, const float* __restrict__ w2,
    const float* __restrict__ b2, const float* __restrict__ luts,
    float* __restrict__ G) {
    int gy = blockIdx.x & 7;
    int c = (blockIdx.x >> 3) % 3;
    int b = blockIdx.x / 24;
    __shared__ float sh1[128][8];
    __shared__ float wk[9][8];
    int tid = threadIdx.x;
    for (int j = tid; j < 1024; j += 256) {
        int ic = j >> 3, gx = j & 7;
        sh1[ic][gx] = h1[(b * 128 + ic) * 64 + gy * 8 + gx];
    }
    __syncthreads();
    if (tid < 72) {
        int k = tid >> 3, gx = tid & 7;
        float acc = b2[c * 9 + k];
        const float* wp = w2 + (c * 9 + k) * 128;
#pragma unroll 8
        for (int ic = 0; ic < 128; ic++) acc = fmaf(__ldg(wp + ic), sh1[ic][gx], acc);
        wk[k][gx] = sigm_f(acc);
    }
    __syncthreads();
    for (int j = tid; j < 2048; j += 256) {
        int gx = j >> 8;
        int i = j & 255;
        float g0 = 0.f, g1 = 0.f;
#pragma unroll
        for (int k = 0; k < 9; k++) {
            const float* lp = luts + (c * 9 + k) * 256;
            float l0 = lp[i];
            float l1 = (i < 255) ? lp[i + 1] : l0;
            g0 = fmaf(wk[k][gx], l0, g0);
            g1 = fmaf(wk[k][gx], l1, g1);
        }
        long o = ((((long)(b * 3 + c) * 8 + gy) * 8 + gx) * 256 + i) * 2;
        G[o] = g0;
        G[o + 1] = g1 - g0;
    }
}

// --------- final: per-pixel 4-corner gather from fused G table --------------
__global__ __launch_bounds__(512) void final_v3(const float* __restrict__ img,
                                                const float* __restrict__ G,
                                                float* __restrict__ out) {
    extern __shared__ float sG[];  // 36864 floats = 147456 B
    int rg = blockIdx.x;
    int b = blockIdx.y;
    int tid = threadIdx.x;
    int h0 = rg * 16;
    const float sc = 7.0f / 1023.0f;

    int g0row = (int)(h0 * sc); if (g0row > 6) g0row = 6;
    int gy_base = (g0row > 5) ? 5 : g0row;

    for (int j = tid; j < 9216; j += 512) {
        int cg = j / 1024;
        int r = j % 1024;
        int c = cg / 3, gyl = cg % 3;
        long src = (((long)(b * 3 + c) * 8 + (gy_base + gyl)) * 8) * 512;
        ((float4*)sG)[cg * 1024 + r] = *(const float4*)(G + src + r * 4);
    }
    __syncthreads();

    int w0 = tid * 2;
    int gxp[2]; float fwp[2];
#pragma unroll
    for (int px = 0; px < 2; px++) {
        float pwv = (w0 + px) * sc;
        int gx = (int)pwv; if (gx > 6) gx = 6;
        gxp[px] = gx;
        fwp[px] = pwv - (float)gx;
    }

    const float2* sgp = (const float2*)sG;

    for (int r = 0; r < 16; r++) {
        int h = h0 + r;
        float ph = h * sc;
        int gy0 = (int)ph; if (gy0 > 6) gy0 = 6;
        float fh = ph - (float)gy0;
        int gyl = gy0 - gy_base;

#pragma unroll
        for (int c = 0; c < 3; c++) {
            long ib = ((long)(b * 3 + c) << 20) + ((long)h << 10) + w0;
            float2 iv = *(const float2*)(img + ib);
            float2 res;
            const float2* crow = sgp + (c * 3 + gyl) * 2048;
#pragma unroll
            for (int px = 0; px < 2; px++) {
                float v = px ? iv.y : iv.x;
                float p = fminf(fmaxf(v, 0.f), 1.f) * 255.0f;
                int i0 = (int)p; if (i0 > 254) i0 = 254;
                float fr = p - (float)i0;
                const float2* b00 = crow + gxp[px] * 256;
                float2 A = b00[i0];
                float2 Bv = b00[256 + i0];
                float2 Cv = b00[2048 + i0];
                float2 Dv = b00[2048 + 256 + i0];
                float va = fmaf(fr, A.y, A.x);
                float vb = fmaf(fr, Bv.y, Bv.x);
                float vc = fmaf(fr, Cv.y, Cv.x);
                float vd = fmaf(fr, Dv.y, Dv.x);
                float fw = fwp[px];
                float top = fmaf(fw, vb - va, va);
                float bot = fmaf(fw, vd - vc, vc);
                float rv = fmaf(fh, bot - top, top);
                rv = fminf(fmaxf(rv, 0.f), 1.f);
                if (px) res.y = rv; else res.x = rv;
            }
            *(float2*)(out + ib) = res;
        }
    }
}

// --------------------------------- launch ----------------------------------
extern "C" void kernel_launch(void* const* d_in, const int* in_sizes, int n_in,
                              void* d_out, int out_size) {
    const float* img     = (const float*)d_in[0];
    const float* conv1_w = (const float*)d_in[1];
    const float* conv1_b = (const float*)d_in[2];
    const float* conv2_w = (const float*)d_in[3];
    const float* conv2_b = (const float*)d_in[4];
    const float* conv3_w = (const float*)d_in[5];
    const float* conv3_b = (const float*)d_in[6];
    const float* conv4_w = (const float*)d_in[7];
    const float* conv4_b = (const float*)d_in[8];
    const float* lin1_w  = (const float*)d_in[9];
    const float* lin1_b  = (const float*)d_in[10];
    const float* lin2_w  = (const float*)d_in[11];
    const float* lin2_b  = (const float*)d_in[12];
    const float* luts    = (const float*)d_in[13];
    float* out = (float*)d_out;

    float *px, *pc1, *pc2, *pc3, *pc4, *pfeat, *ph1, *pwT, *plp, *pcp, *pwr, *pG;
    cudaGetSymbolAddress((void**)&px, g_x);
    cudaGetSymbolAddress((void**)&pc1, g_c1);
    cudaGetSymbolAddress((void**)&pc2, g_c2);
    cudaGetSymbolAddress((void**)&pc3, g_c3);
    cudaGetSymbolAddress((void**)&pc4, g_c4);
    cudaGetSymbolAddress((void**)&pfeat, g_feat);
    cudaGetSymbolAddress((void**)&ph1, g_h1);
    cudaGetSymbolAddress((void**)&pwT, g_wT);
    cudaGetSymbolAddress((void**)&plp, g_lpart);
    cudaGetSymbolAddress((void**)&pcp, g_cpart);
    cudaGetSymbolAddress((void**)&pwr, g_wrep);
    cudaGetSymbolAddress((void**)&pG, g_G);

    cudaFuncSetAttribute(final_v3, cudaFuncAttributeMaxDynamicSharedMemorySize, 147456);

    // 0. prep: weight repacks + lin1 transpose
    prep_kernel<<<3676, 256>>>(conv1_w, conv2_w, conv3_w, conv4_w, lin1_w, pwr, pwT);

    // 1. resize 1024 -> 256
    resize256_kernel<<<1536, 256>>>(img, px);

    // 2-5. conv stack (R4 structure, ocg-fastest lane map)
    conv_v3<3, 32, 256, true><<<dim3(128, 1), 256>>>(px, pwr + WR1_OFF, conv1_b, pc1, 3);

    conv_v3<8, 64, 128, false><<<dim3(64, 4), 256>>>(pc1, pwr + WR2_OFF, conv2_b, pcp, 32);
    reduce_silu_kernel<<<2048, 256>>>(pcp, pc2, 524288, 4);

    conv_v3<8, 128, 64, false><<<dim3(32, 8), 256>>>(pc2, pwr + WR3_OFF, conv3_b, pcp, 64);
    reduce_silu_kernel<<<1024, 256>>>(pcp, pc3, 262144, 8);

    conv_v3<8, 256, 32, false><<<dim3(16, 16), 256>>>(pc3, pwr + WR4_OFF, conv4_b, pcp, 128);
    reduce_silu_kernel<<<512, 256>>>(pcp, pc4, 131072, 16);

    // 6. merged multi-scale avg pools
    pool_all_kernel<<<7680, 256>>>(pc1, pc2, pc3, pc4, pfeat);

    // 7. lin1 (480->128, 3x3 reflect, SiLU), split-K x30
    lin1_kernel<<<dim3(30, 8, 2), 128>>>(pfeat, pwT, plp);
    lin1_reduce_kernel<<<64, 256>>>(plp, lin1_b, ph1);

    // 8+9. fused lin2 + G table
    gprep2_kernel<<<48, 256>>>(ph1, lin2_w, lin2_b, luts, pG);

    // 10. final: 4-corner gather + clip
    final_v3<<<dim3(64, 2), 512, 147456>>>(img, pG, out);
}